// round 10
// baseline (speedup 1.0000x reference)
#include <cuda_runtime.h>
#include <math.h>

#define W 512
#define H 512
#define HW (H * W)            // 262144
#define TWO_PI 6.283185307179586f
#define ALPHA_THRESH (1.0f / 255.0f)

#define NB 512                // blocks; 4/SM guaranteed -> all wave-1 resident
#define NT 256                // threads/block
#define NTHREADS (NB * NT)    // 131072 = HW/2
#define NWARPS (NB * 8)       // 4096

// Interleaved accumulation plane: (c0, c1, c2, junk) per pixel.
// Zero-initialized BSS; phase 2 re-zeroes it every replay.
__device__ float4 g_accum[HW];
__device__ int g_arrive;      // grid barrier state; last finisher resets
__device__ int g_done;

__global__ __launch_bounds__(NT, 4) void fused_kernel(
        const float* __restrict__ xyz,
        const float* __restrict__ scaling,
        const float* __restrict__ rot,
        const float* __restrict__ feat,
        const float* __restrict__ opac,
        float* __restrict__ out,
        int n) {
    int tid = threadIdx.x;
    int bid = blockIdx.x;
    int lane = tid & 31;

    // ---------------- Phase 1: splat (warp per gaussian, strided) ----------------
    for (int g = bid * 8 + (tid >> 5); g < n; g += NWARPS) {
        float2 xy = ((const float2*)xyz)[g];
        float2 sc = ((const float2*)scaling)[g];
        float mx = tanhf(xy.x);
        float my = tanhf(xy.y);
        float sx = fabsf(sc.x + 0.5f);
        float sy = fabsf(sc.y + 0.5f);
        float theta = (1.0f / (1.0f + expf(-rot[g]))) * TWO_PI;

        float cx = 0.5f * ((mx + 1.0f) * (float)W - 1.0f);
        float cy = 0.5f * ((my + 1.0f) * (float)H - 1.0f);

        float sth, cth;
        sincosf(theta, &sth, &cth);
        float sx2 = sx * sx;
        float sy2 = sy * sy;
        float a = cth * cth * sx2 + sth * sth * sy2;
        float b = cth * sth * (sx2 - sy2);
        float c = sth * sth * sx2 + cth * cth * sy2;
        float det = a * c - b * b;
        float op = opac[g];
        float tmax = logf(op * 255.0f);   // alpha > 1/255 <=> sigma < tmax
        if (!(det > 0.0f) || !(tmax > 0.0f)) continue;

        float inv_det = 1.0f / fmaxf(det, 1e-12f);
        float hA = 0.5f * c * inv_det;
        float B  = -b * inv_det;
        float hC = 0.5f * a * inv_det;

        // a,c <= 2.25, tmax <= ln(255) => rx,ry <= ~6.1 => bbox width <= 13 < 16
        float rx = sqrtf(2.0f * tmax * a) + 1.0f;
        float ry = sqrtf(2.0f * tmax * c) + 1.0f;

        int x0 = max(0, (int)ceilf(cx - rx));
        int x1 = min(W - 1, (int)floorf(cx + rx));
        int y0 = max(0, (int)ceilf(cy - ry));
        int y1 = min(H - 1, (int)floorf(cy + ry));
        if (x1 < x0 || y1 < y0) continue;

        float c0 = op * feat[3 * g];
        float c1 = op * feat[3 * g + 1];
        float c2 = op * feat[3 * g + 2];

        // lanes 0-15: even rows, 16-31: odd rows; lane&15 indexes x
        int px = x0 + (lane & 15);
        float dx = cx - (float)px;
        float sxx = hA * dx * dx;
        float bdx = B * dx;
        bool xin = (px <= x1);

        for (int py = y0 + (lane >> 4); py <= y1; py += 2) {
            float dy = cy - (float)py;
            float sigma = fmaf(hC, dy, bdx) * dy + sxx;
            float w = __expf(-sigma);
            float alpha = op * w;
            if (xin && sigma >= 0.0f && alpha > ALPHA_THRESH) {
                float4* dst = &g_accum[py * W + px];
                asm volatile("red.global.add.v4.f32 [%0], {%1, %2, %3, %4};"
                             :: "l"(dst), "f"(w * c0), "f"(w * c1),
                                "f"(w * c2), "f"(0.0f)
                             : "memory");
            }
        }
    }

    // ---------------- grid barrier ----------------
    __threadfence();
    __syncthreads();
    if (tid == 0) {
        atomicAdd(&g_arrive, 1);
        while (*((volatile int*)&g_arrive) < NB) { }
        // all blocks have arrived; count passages so last one can reset state
        int d = atomicAdd(&g_done, 1);
        if (d == NB - 1) {
            g_arrive = 0;
            g_done = 0;
        }
    }
    __syncthreads();
    __threadfence();   // acquire: order phase-2 loads after observed reds

    // ---------------- Phase 2: finalize (2 px per thread) ----------------
    int t = bid * NT + tid;

    float4 v0 = g_accum[t];
    float4 v1 = g_accum[t + NTHREADS];

    float4 z = make_float4(0.0f, 0.0f, 0.0f, 0.0f);
    g_accum[t]            = z;      // re-arm for next graph replay
    g_accum[t + NTHREADS] = z;

    #define CLAMP(x) fminf(fmaxf((x), 0.0f), 1.0f)
    __stcs(&out[t],                       CLAMP(v0.x));
    __stcs(&out[t + NTHREADS],            CLAMP(v1.x));
    __stcs(&out[HW + t],                  CLAMP(v0.y));
    __stcs(&out[HW + t + NTHREADS],       CLAMP(v1.y));
    __stcs(&out[2 * HW + t],              CLAMP(v0.z));
    __stcs(&out[2 * HW + t + NTHREADS],   CLAMP(v1.z));
    #undef CLAMP
}

extern "C" void kernel_launch(void* const* d_in, const int* in_sizes, int n_in,
                              void* d_out, int out_size) {
    const float* xyz     = (const float*)d_in[0];  // (N,2)
    const float* scaling = (const float*)d_in[1];  // (N,2)
    const float* rot     = (const float*)d_in[2];  // (N,1)
    const float* feat    = (const float*)d_in[3];  // (N,3)
    const float* opac    = (const float*)d_in[4];  // (N,1)
    float* out = (float*)d_out;                     // (1,3,512,512)

    int n = in_sizes[0] / 2;

    fused_kernel<<<NB, NT>>>(xyz, scaling, rot, feat, opac, out, n);
}

// round 11
// speedup vs baseline: 1.0151x; 1.0151x over previous
#include <cuda_runtime.h>
#include <math.h>

#define W 512
#define H 512
#define HW (H * W)            // 262144
#define QW (HW / 4)           // 65536
#define TWO_PI 6.283185307179586f
#define ALPHA_THRESH (1.0f / 255.0f)

#define NB 256                // blocks, all co-resident (4/SM guaranteed)
#define NT 256
#define NWARPS (NB * 8)       // 2048
#define NLEAF 16              // barrier tree fan-in: 16 leaves x 16 blocks

// Interleaved accumulation plane: (c0, c1, c2, junk) per pixel.
// Zero-initialized BSS; phase 2 re-zeroes it every replay.
__device__ float4 g_accum[HW];
// barrier state (all zero-init; self-resetting every replay)
__device__ int g_leaf[NLEAF];
__device__ int g_root;
__device__ volatile int g_flag;
__device__ int g_dleaf[NLEAF];
__device__ int g_droot;

__global__ __launch_bounds__(NT, 4) void fused_kernel(
        const float* __restrict__ xyz,
        const float* __restrict__ scaling,
        const float* __restrict__ rot,
        const float* __restrict__ feat,
        const float* __restrict__ opac,
        float* __restrict__ out,
        int n) {
    int tid = threadIdx.x;
    int bid = blockIdx.x;
    int lane = tid & 31;

    // ---------------- Phase 1: splat (warp per gaussian, strided) ----------------
    for (int g = bid * 8 + (tid >> 5); g < n; g += NWARPS) {
        float2 xy = ((const float2*)xyz)[g];
        float2 sc = ((const float2*)scaling)[g];
        float mx = tanhf(xy.x);
        float my = tanhf(xy.y);
        float sx = fabsf(sc.x + 0.5f);
        float sy = fabsf(sc.y + 0.5f);
        float theta = (1.0f / (1.0f + expf(-rot[g]))) * TWO_PI;

        float cx = 0.5f * ((mx + 1.0f) * (float)W - 1.0f);
        float cy = 0.5f * ((my + 1.0f) * (float)H - 1.0f);

        float sth, cth;
        sincosf(theta, &sth, &cth);
        float sx2 = sx * sx;
        float sy2 = sy * sy;
        float a = cth * cth * sx2 + sth * sth * sy2;
        float b = cth * sth * (sx2 - sy2);
        float c = sth * sth * sx2 + cth * cth * sy2;
        float det = a * c - b * b;
        float op = opac[g];
        float tmax = logf(op * 255.0f);   // alpha > 1/255 <=> sigma < tmax
        if (!(det > 0.0f) || !(tmax > 0.0f)) continue;

        float inv_det = 1.0f / fmaxf(det, 1e-12f);
        float hA = 0.5f * c * inv_det;
        float B  = -b * inv_det;
        float hC = 0.5f * a * inv_det;

        // a,c <= 2.25, tmax <= ln(255) => rx,ry <= ~6 => bbox width <= 13 < 16
        float rx = sqrtf(2.0f * tmax * a) + 1.0f;
        float ry = sqrtf(2.0f * tmax * c) + 1.0f;

        int x0 = max(0, (int)ceilf(cx - rx));
        int x1 = min(W - 1, (int)floorf(cx + rx));
        int y0 = max(0, (int)ceilf(cy - ry));
        int y1 = min(H - 1, (int)floorf(cy + ry));
        if (x1 < x0 || y1 < y0) continue;

        float c0 = op * feat[3 * g];
        float c1 = op * feat[3 * g + 1];
        float c2 = op * feat[3 * g + 2];

        // lanes 0-15: even rows, 16-31: odd rows; lane&15 indexes x
        int px = x0 + (lane & 15);
        float dx = cx - (float)px;
        float sxx = hA * dx * dx;
        float bdx = B * dx;
        bool xin = (px <= x1);

        for (int py = y0 + (lane >> 4); py <= y1; py += 2) {
            float dy = cy - (float)py;
            float sigma = fmaf(hC, dy, bdx) * dy + sxx;
            float w = __expf(-sigma);
            float alpha = op * w;
            if (xin && sigma >= 0.0f && alpha > ALPHA_THRESH) {
                float4* dst = &g_accum[py * W + px];
                asm volatile("red.global.add.v4.f32 [%0], {%1, %2, %3, %4};"
                             :: "l"(dst), "f"(w * c0), "f"(w * c1),
                                "f"(w * c2), "f"(0.0f)
                             : "memory");
            }
        }
    }

    // ---------------- tree grid barrier (16x16, no flat 256-way atomic chain) ----
    __threadfence();
    __syncthreads();
    if (tid == 0) {
        int l = bid & (NLEAF - 1);
        int r = atomicAdd(&g_leaf[l], 1);
        if (r == NB / NLEAF - 1) {            // last at this leaf
            g_leaf[l] = 0;                    // re-arm leaf (no one else reads it)
            int r2 = atomicAdd(&g_root, 1);
            if (r2 == NLEAF - 1) {            // last leaf in
                g_root = 0;                   // re-arm root
                __threadfence();
                g_flag = 1;                   // release
            }
        }
        while (g_flag == 0) { }
    }
    __syncthreads();
    __threadfence();                          // acquire side

    // ---------------- Phase 2: finalize (4 px per thread, MLP=4) ----------------
    int t = bid * NT + tid;                   // 65536 threads exactly

    float4 v0 = g_accum[t];
    float4 v1 = g_accum[t + QW];
    float4 v2 = g_accum[t + 2 * QW];
    float4 v3 = g_accum[t + 3 * QW];

    float4 z = make_float4(0.0f, 0.0f, 0.0f, 0.0f);
    g_accum[t]          = z;                  // re-arm for next graph replay
    g_accum[t + QW]     = z;
    g_accum[t + 2 * QW] = z;
    g_accum[t + 3 * QW] = z;

    #define CLAMP(x) fminf(fmaxf((x), 0.0f), 1.0f)
    __stcs(&out[t],                    CLAMP(v0.x));
    __stcs(&out[t + QW],               CLAMP(v1.x));
    __stcs(&out[t + 2 * QW],           CLAMP(v2.x));
    __stcs(&out[t + 3 * QW],           CLAMP(v3.x));

    __stcs(&out[HW + t],               CLAMP(v0.y));
    __stcs(&out[HW + t + QW],          CLAMP(v1.y));
    __stcs(&out[HW + t + 2 * QW],      CLAMP(v2.y));
    __stcs(&out[HW + t + 3 * QW],      CLAMP(v3.y));

    __stcs(&out[2 * HW + t],           CLAMP(v0.z));
    __stcs(&out[2 * HW + t + QW],      CLAMP(v1.z));
    __stcs(&out[2 * HW + t + 2 * QW],  CLAMP(v2.z));
    __stcs(&out[2 * HW + t + 3 * QW],  CLAMP(v3.z));
    #undef CLAMP

    // ---------------- done-tree: reset flag for next replay ----------------
    __syncthreads();
    if (tid == 0) {
        int l = bid & (NLEAF - 1);
        int r = atomicAdd(&g_dleaf[l], 1);
        if (r == NB / NLEAF - 1) {
            g_dleaf[l] = 0;
            int r2 = atomicAdd(&g_droot, 1);
            if (r2 == NLEAF - 1) {            // very last block through
                g_droot = 0;
                g_flag = 0;                   // safe: everyone has passed barrier
                __threadfence();
            }
        }
    }
}

extern "C" void kernel_launch(void* const* d_in, const int* in_sizes, int n_in,
                              void* d_out, int out_size) {
    const float* xyz     = (const float*)d_in[0];  // (N,2)
    const float* scaling = (const float*)d_in[1];  // (N,2)
    const float* rot     = (const float*)d_in[2];  // (N,1)
    const float* feat    = (const float*)d_in[3];  // (N,3)
    const float* opac    = (const float*)d_in[4];  // (N,1)
    float* out = (float*)d_out;                     // (1,3,512,512)

    int n = in_sizes[0] / 2;

    fused_kernel<<<NB, NT>>>(xyz, scaling, rot, feat, opac, out, n);
}

// round 12
// speedup vs baseline: 1.3732x; 1.3528x over previous
#include <cuda_runtime.h>
#include <math.h>

#define W 512
#define H 512
#define HW (H * W)          // 262144
#define QW (HW / 4)         // 65536
#define TWO_PI 6.283185307179586f
#define ALPHA_THRESH (1.0f / 255.0f)

// Interleaved accumulation plane: (c0, c1, c2, junk) per pixel.
// .w is NEVER written (stays BSS-zero); finalize re-zeroes .xyz every replay.
__device__ float4 g_accum[HW];

__global__ __launch_bounds__(256) void splat_kernel(
        const float* __restrict__ xyz,
        const float* __restrict__ scaling,
        const float* __restrict__ rot,
        const float* __restrict__ feat,
        const float* __restrict__ opac,
        int n) {
    int g = (blockIdx.x * blockDim.x + threadIdx.x) >> 5;
    int lane = threadIdx.x & 31;

    if (g < n) {
        // Per-gaussian prep (all lanes redundantly; loads broadcast via L1)
        float2 xy = ((const float2*)xyz)[g];
        float2 sc = ((const float2*)scaling)[g];
        float mx = tanhf(xy.x);
        float my = tanhf(xy.y);
        float sx = fabsf(sc.x + 0.5f);
        float sy = fabsf(sc.y + 0.5f);
        float theta = (1.0f / (1.0f + expf(-rot[g]))) * TWO_PI;

        float cx = 0.5f * ((mx + 1.0f) * (float)W - 1.0f);
        float cy = 0.5f * ((my + 1.0f) * (float)H - 1.0f);

        float sth, cth;
        sincosf(theta, &sth, &cth);
        float sx2 = sx * sx;
        float sy2 = sy * sy;
        float a = cth * cth * sx2 + sth * sth * sy2;
        float b = cth * sth * (sx2 - sy2);
        float c = sth * sth * sx2 + cth * cth * sy2;
        float det = a * c - b * b;
        float op = opac[g];
        float tmax = logf(op * 255.0f);     // alpha > 1/255 <=> sigma < tmax

        if (det > 0.0f && tmax > 0.0f) {
            float inv_det = 1.0f / fmaxf(det, 1e-12f);
            float hA = 0.5f * c * inv_det;      // 0.5*A
            float B  = -b * inv_det;
            float hC = 0.5f * a * inv_det;      // 0.5*C

            // a,c <= 2.25, tmax <= ln(255) => rx,ry <= ~6.1 => bbox width <= 13 < 16
            float rx = sqrtf(2.0f * tmax * a) + 1.0f;
            float ry = sqrtf(2.0f * tmax * c) + 1.0f;

            int x0 = max(0, (int)ceilf(cx - rx));
            int x1 = min(W - 1, (int)floorf(cx + rx));
            int y0 = max(0, (int)ceilf(cy - ry));
            int y1 = min(H - 1, (int)floorf(cy + ry));

            if (x1 >= x0 && y1 >= y0) {
                float c0 = op * feat[3 * g];
                float c1 = op * feat[3 * g + 1];
                float c2 = op * feat[3 * g + 2];

                // lanes 0-15: even rows, lanes 16-31: odd rows; lane&15 indexes x
                int px = x0 + (lane & 15);
                float dx = cx - (float)px;
                float sxx = hA * dx * dx;
                float bdx = B * dx;
                bool xin = (px <= x1);

                for (int py = y0 + (lane >> 4); py <= y1; py += 2) {
                    float dy = cy - (float)py;
                    float sigma = fmaf(hC, dy, bdx) * dy + sxx;
                    float w = __expf(-sigma);
                    float alpha = op * w;
                    if (xin && sigma >= 0.0f && alpha > ALPHA_THRESH) {
                        float* dst = (float*)&g_accum[py * W + px];
                        // 3 words instead of 4: v2 + scalar (REDG is word-cost bound)
                        asm volatile("red.global.add.v2.f32 [%0], {%1, %2};"
                                     :: "l"(dst), "f"(w * c0), "f"(w * c1)
                                     : "memory");
                        asm volatile("red.global.add.f32 [%0], %1;"
                                     :: "l"(dst + 2), "f"(w * c2)
                                     : "memory");
                    }
                }
            }
        }
    }

    // allow the dependent finalize kernel to launch/ramp now
    asm volatile("griddepcontrol.launch_dependents;");
}

__global__ __launch_bounds__(256) void finalize_kernel(float* __restrict__ out) {
    int t = blockIdx.x * blockDim.x + threadIdx.x;   // 65536 threads, 4 px each

    // wait until splat's memory is visible
    asm volatile("griddepcontrol.wait;");

    // 4 independent L2-only loads up front -> MLP = 4 per thread
    float4 v0 = __ldcg(&g_accum[t]);
    float4 v1 = __ldcg(&g_accum[t + QW]);
    float4 v2 = __ldcg(&g_accum[t + 2 * QW]);
    float4 v3 = __ldcg(&g_accum[t + 3 * QW]);

    float4 z = make_float4(0.0f, 0.0f, 0.0f, 0.0f);
    g_accum[t]          = z;           // re-arm for next graph replay
    g_accum[t + QW]     = z;
    g_accum[t + 2 * QW] = z;
    g_accum[t + 3 * QW] = z;

    #define CLAMP(x) fminf(fmaxf((x), 0.0f), 1.0f)
    __stcs(&out[t],                    CLAMP(v0.x));
    __stcs(&out[t + QW],               CLAMP(v1.x));
    __stcs(&out[t + 2 * QW],           CLAMP(v2.x));
    __stcs(&out[t + 3 * QW],           CLAMP(v3.x));

    __stcs(&out[HW + t],               CLAMP(v0.y));
    __stcs(&out[HW + t + QW],          CLAMP(v1.y));
    __stcs(&out[HW + t + 2 * QW],      CLAMP(v2.y));
    __stcs(&out[HW + t + 3 * QW],      CLAMP(v3.y));

    __stcs(&out[2 * HW + t],           CLAMP(v0.z));
    __stcs(&out[2 * HW + t + QW],      CLAMP(v1.z));
    __stcs(&out[2 * HW + t + 2 * QW],  CLAMP(v2.z));
    __stcs(&out[2 * HW + t + 3 * QW],  CLAMP(v3.z));
    #undef CLAMP
}

extern "C" void kernel_launch(void* const* d_in, const int* in_sizes, int n_in,
                              void* d_out, int out_size) {
    const float* xyz     = (const float*)d_in[0];  // (N,2)
    const float* scaling = (const float*)d_in[1];  // (N,2)
    const float* rot     = (const float*)d_in[2];  // (N,1)
    const float* feat    = (const float*)d_in[3];  // (N,3)
    const float* opac    = (const float*)d_in[4];  // (N,1)
    float* out = (float*)d_out;                     // (1,3,512,512)

    int n = in_sizes[0] / 2;

    int blocks = (n + 7) / 8;                       // 8 warps/block, 1 gaussian/warp
    splat_kernel<<<blocks, 256>>>(xyz, scaling, rot, feat, opac, n);

    // finalize launched as a programmatic dependent: ramps while splat runs
    cudaLaunchConfig_t cfg = {};
    cfg.gridDim  = dim3(QW / 256);
    cfg.blockDim = dim3(256);
    cfg.dynamicSmemBytes = 0;
    cfg.stream = 0;
    cudaLaunchAttribute attr[1];
    attr[0].id = cudaLaunchAttributeProgrammaticStreamSerialization;
    attr[0].val.programmaticStreamSerializationAllowed = 1;
    cfg.attrs = attr;
    cfg.numAttrs = 1;
    cudaLaunchKernelEx(&cfg, finalize_kernel, out);
}